// round 1
// baseline (speedup 1.0000x reference)
#include <cuda_runtime.h>

typedef unsigned long long u64;

// ---------- packed f32x2 helpers (sm_103a) ----------
__device__ __forceinline__ u64 fma2(u64 a, u64 b, u64 c) {
    u64 d;
    asm("fma.rn.f32x2 %0, %1, %2, %3;" : "=l"(d) : "l"(a), "l"(b), "l"(c));
    return d;
}
__device__ __forceinline__ u64 pack2(float lo, float hi) {
    u64 d;
    asm("mov.b64 %0, {%1, %2};" : "=l"(d) : "f"(lo), "f"(hi));
    return d;
}
__device__ __forceinline__ float2 unpack2(u64 v) {
    float2 r;
    asm("mov.b64 {%0, %1}, %2;" : "=f"(r.x), "=f"(r.y) : "l"(v));
    return r;
}
__device__ __forceinline__ float red8(u64 a0, u64 a1, u64 a2, u64 a3) {
    float2 f0 = unpack2(a0), f1 = unpack2(a1), f2 = unpack2(a2), f3 = unpack2(a3);
    return ((f0.x + f0.y) + (f1.x + f1.y)) + ((f2.x + f2.y) + (f3.x + f3.y));
}

// ---------- transposed first-layer weights (scratch: __device__ globals) ----------
__device__ __align__(16) float g_sig0T[64 * 32];   // [out][in]
__device__ __align__(16) float g_col0T[64 * 64];
__device__ __align__(16) float g_vis0T[64 * 48];

__global__ void prep_kernel(const float* __restrict__ ws0,
                            const float* __restrict__ wc0,
                            const float* __restrict__ wv0) {
    int t = blockIdx.x * blockDim.x + threadIdx.x;
    int stride = gridDim.x * blockDim.x;
    for (int idx = t; idx < 64 * 32; idx += stride) {
        int j = idx >> 5, i = idx & 31;
        g_sig0T[idx] = ws0[i * 64 + j];
    }
    for (int idx = t; idx < 64 * 64; idx += stride) {
        int j = idx >> 6, i = idx & 63;
        g_col0T[idx] = wc0[i * 64 + j];
    }
    for (int idx = t; idx < 64 * 48; idx += stride) {
        int j = idx / 48, i = idx % 48;
        g_vis0T[idx] = wv0[i * 64 + j];
    }
}

// ---------- SH degree-4 (16 comps), matches reference ----------
__device__ __forceinline__ void sh16(float x, float y, float z, float* e) {
    float xx = x * x, yy = y * y, zz = z * z;
    float xy = x * y, yz = y * z, xz = x * z;
    e[0]  = 0.28209479177387814f;
    e[1]  = -0.48860251190291987f * y;
    e[2]  = 0.48860251190291987f * z;
    e[3]  = -0.48860251190291987f * x;
    e[4]  = 1.0925484305920792f * xy;
    e[5]  = -1.0925484305920792f * yz;
    e[6]  = 0.94617469575756f * zz - 0.31539156525252005f;
    e[7]  = -1.0925484305920792f * xz;
    e[8]  = 0.5462742152960396f * (xx - yy);
    e[9]  = 0.5900435899266435f * y * (3.0f * xx - yy);
    e[10] = 2.890611442640554f * xy * z;
    e[11] = 0.4570457994644657f * y * (4.0f * zz - xx - yy);
    e[12] = 0.3731763325901154f * z * (2.0f * zz - 3.0f * xx - 3.0f * yy);
    e[13] = 0.4570457994644657f * x * (4.0f * zz - xx - yy);
    e[14] = 1.445305721320277f * z * (xx - yy);
    e[15] = 0.5900435899266435f * x * (xx - 3.0f * yy);
}

#define THREADS 256
#define SMEM_FLOATS 15552   // 2048 + 1024 + 4096 + 5056 + 192 + 3072 + 64
#define SMEM_BYTES (SMEM_FLOATS * 4)

__global__ void __launch_bounds__(THREADS, 1)
nerf_kernel(const float* __restrict__ x_feat,
            const float* __restrict__ dvec,
            const float* __restrict__ lvec,
            const float* __restrict__ w_sig1,   // [64,16] row-major
            const float* __restrict__ w_col1,   // [79,64] row-major
            const float* __restrict__ w_col2,   // [64,3]  row-major
            const float* __restrict__ w_vis1,   // [64]
            float* __restrict__ out, int N) {
    extern __shared__ float sm[];
    float* s_sig0T = sm;            // 2048  [64][32]
    float* s_sig1  = sm + 2048;     // 1024  [64][16]
    float* s_col0T = sm + 3072;     // 4096  [64][64]
    float* s_col1  = sm + 7168;     // 5056  [79][64]
    float* s_col2  = sm + 12224;    // 192   [64][3]
    float* s_vis0T = sm + 12416;    // 3072  [64][48]
    float* s_vis1  = sm + 15488;    // 64

    // ---- cooperative weight staging (all float4, all sizes divisible by 4) ----
    {
        int t = threadIdx.x;
        const float4* s;
        s = (const float4*)g_sig0T;
        for (int i = t; i < 512; i += THREADS) ((float4*)s_sig0T)[i] = s[i];
        s = (const float4*)w_sig1;
        for (int i = t; i < 256; i += THREADS) ((float4*)s_sig1)[i] = s[i];
        s = (const float4*)g_col0T;
        for (int i = t; i < 1024; i += THREADS) ((float4*)s_col0T)[i] = s[i];
        s = (const float4*)w_col1;
        for (int i = t; i < 1264; i += THREADS) ((float4*)s_col1)[i] = s[i];
        s = (const float4*)w_col2;
        for (int i = t; i < 48; i += THREADS) ((float4*)s_col2)[i] = s[i];
        s = (const float4*)g_vis0T;
        for (int i = t; i < 768; i += THREADS) ((float4*)s_vis0T)[i] = s[i];
        s = (const float4*)w_vis1;
        if (t < 16) ((float4*)s_vis1)[t] = s[t];
    }
    __syncthreads();

    int n = blockIdx.x * THREADS + threadIdx.x;
    if (n >= N) return;

    // ---- per-point inputs ----
    float de[16], le[16];
    {
        const float* dp = dvec + 3 * (size_t)n;
        sh16(dp[0], dp[1], dp[2], de);
        const float* lp = lvec + 3 * (size_t)n;
        sh16(lp[0], lp[1], lp[2], le);
    }
    u64 pdv[8], plv[8], px[16];
#pragma unroll
    for (int i = 0; i < 8; i++) {
        pdv[i] = pack2(de[2 * i], de[2 * i + 1]);
        plv[i] = pack2(le[2 * i], le[2 * i + 1]);
    }
    {
        const ulonglong2* xp = (const ulonglong2*)(x_feat + 32 * (size_t)n);
#pragma unroll
        for (int i = 0; i < 8; i++) {
            ulonglong2 v = xp[i];
            px[2 * i] = v.x;
            px[2 * i + 1] = v.y;
        }
    }

    // ---- vis net: relu([x,l] @ w_vis0) @ w_vis1 -> sigmoid (fully fused) ----
    float visacc = 0.f;
#pragma unroll 1
    for (int j = 0; j < 64; j++) {
        const ulonglong2* w = (const ulonglong2*)(s_vis0T + j * 48);
        u64 a[4] = {0ull, 0ull, 0ull, 0ull};
#pragma unroll
        for (int ii = 0; ii < 8; ii++) {
            ulonglong2 wv = w[ii];
            a[(2 * ii) & 3]     = fma2(px[2 * ii],     wv.x, a[(2 * ii) & 3]);
            a[(2 * ii + 1) & 3] = fma2(px[2 * ii + 1], wv.y, a[(2 * ii + 1) & 3]);
        }
#pragma unroll
        for (int ii = 0; ii < 4; ii++) {
            ulonglong2 wv = w[8 + ii];
            a[(2 * ii) & 3]     = fma2(plv[2 * ii],     wv.x, a[(2 * ii) & 3]);
            a[(2 * ii + 1) & 3] = fma2(plv[2 * ii + 1], wv.y, a[(2 * ii + 1) & 3]);
        }
        float h = fmaxf(red8(a[0], a[1], a[2], a[3]), 0.f);
        visacc = fmaf(h, s_vis1[j], visacc);
    }
    float vis = 1.f / (1.f + expf(-visacc));

    // ---- sigma net: relu(x @ w_sig0) @ w_sig1; keep geo = out[1:16] ----
    u64 sa[8] = {0ull, 0ull, 0ull, 0ull, 0ull, 0ull, 0ull, 0ull};
#pragma unroll 1
    for (int j = 0; j < 64; j++) {
        const ulonglong2* w = (const ulonglong2*)(s_sig0T + j * 32);
        u64 a[4] = {0ull, 0ull, 0ull, 0ull};
#pragma unroll
        for (int ii = 0; ii < 8; ii++) {
            ulonglong2 wv = w[ii];
            a[(2 * ii) & 3]     = fma2(px[2 * ii],     wv.x, a[(2 * ii) & 3]);
            a[(2 * ii + 1) & 3] = fma2(px[2 * ii + 1], wv.y, a[(2 * ii + 1) & 3]);
        }
        float h = fmaxf(red8(a[0], a[1], a[2], a[3]), 0.f);
        u64 hh = pack2(h, h);
        const ulonglong2* w1 = (const ulonglong2*)(s_sig1 + j * 16);
#pragma unroll
        for (int ii = 0; ii < 4; ii++) {
            ulonglong2 wv = w1[ii];
            sa[2 * ii]     = fma2(hh, wv.x, sa[2 * ii]);
            sa[2 * ii + 1] = fma2(hh, wv.y, sa[2 * ii + 1]);
        }
    }
    float geo[15];
    {
        float2 p = unpack2(sa[0]);
        geo[0] = p.y;
#pragma unroll
        for (int k = 1; k < 8; k++) {
            p = unpack2(sa[k]);
            geo[2 * k - 1] = p.x;
            geo[2 * k] = p.y;
        }
    }

    // ---- color net: col0 fused into col1 accumulation ----
    u64 ca[32];
#pragma unroll
    for (int k = 0; k < 32; k++) ca[k] = 0ull;

#pragma unroll 1
    for (int j = 0; j < 64; j++) {
        const ulonglong2* w = (const ulonglong2*)(s_col0T + j * 64);
        u64 a[4] = {0ull, 0ull, 0ull, 0ull};
#pragma unroll
        for (int ii = 0; ii < 8; ii++) {   // x part (inputs 0..31)
            ulonglong2 wv = w[ii];
            a[(2 * ii) & 3]     = fma2(px[2 * ii],     wv.x, a[(2 * ii) & 3]);
            a[(2 * ii + 1) & 3] = fma2(px[2 * ii + 1], wv.y, a[(2 * ii + 1) & 3]);
        }
#pragma unroll
        for (int ii = 0; ii < 4; ii++) {   // l_enc part (32..47)
            ulonglong2 wv = w[8 + ii];
            a[(2 * ii) & 3]     = fma2(plv[2 * ii],     wv.x, a[(2 * ii) & 3]);
            a[(2 * ii + 1) & 3] = fma2(plv[2 * ii + 1], wv.y, a[(2 * ii + 1) & 3]);
        }
#pragma unroll
        for (int ii = 0; ii < 4; ii++) {   // d_enc part (48..63)
            ulonglong2 wv = w[12 + ii];
            a[(2 * ii) & 3]     = fma2(pdv[2 * ii],     wv.x, a[(2 * ii) & 3]);
            a[(2 * ii + 1) & 3] = fma2(pdv[2 * ii + 1], wv.y, a[(2 * ii + 1) & 3]);
        }
        float h = fmaxf(red8(a[0], a[1], a[2], a[3]), 0.f);
        u64 hh = pack2(h, h);
        const ulonglong2* w1 = (const ulonglong2*)(s_col1 + j * 64);
#pragma unroll
        for (int ii = 0; ii < 16; ii++) {
            ulonglong2 wv = w1[ii];
            ca[2 * ii]     = fma2(hh, wv.x, ca[2 * ii]);
            ca[2 * ii + 1] = fma2(hh, wv.y, ca[2 * ii + 1]);
        }
    }
    // geo tail of col1 input (rows 64..78)
#pragma unroll
    for (int g = 0; g < 15; g++) {
        u64 gg = pack2(geo[g], geo[g]);
        const ulonglong2* w1 = (const ulonglong2*)(s_col1 + (64 + g) * 64);
#pragma unroll
        for (int ii = 0; ii < 16; ii++) {
            ulonglong2 wv = w1[ii];
            ca[2 * ii]     = fma2(gg, wv.x, ca[2 * ii]);
            ca[2 * ii + 1] = fma2(gg, wv.y, ca[2 * ii + 1]);
        }
    }

    // ---- col2 + relu + vis scale ----
    float c0 = 0.f, c1 = 0.f, c2 = 0.f;
#pragma unroll
    for (int k2 = 0; k2 < 32; k2++) {
        float2 p = unpack2(ca[k2]);
        float v0 = fmaxf(p.x, 0.f), v1 = fmaxf(p.y, 0.f);
        const float* wr = s_col2 + 6 * k2;
        c0 = fmaf(v0, wr[0], c0);
        c1 = fmaf(v0, wr[1], c1);
        c2 = fmaf(v0, wr[2], c2);
        c0 = fmaf(v1, wr[3], c0);
        c1 = fmaf(v1, wr[4], c1);
        c2 = fmaf(v1, wr[5], c2);
    }
    float* o = out + 3 * (size_t)n;
    o[0] = fmaxf(c0, 0.f) * vis;
    o[1] = fmaxf(c1, 0.f) * vis;
    o[2] = fmaxf(c2, 0.f) * vis;
}

extern "C" void kernel_launch(void* const* d_in, const int* in_sizes, int n_in,
                              void* d_out, int out_size) {
    const float* x_feat = (const float*)d_in[0];
    const float* dv     = (const float*)d_in[1];
    const float* lv     = (const float*)d_in[2];
    const float* w_sig0 = (const float*)d_in[3];
    const float* w_sig1 = (const float*)d_in[4];
    const float* w_col0 = (const float*)d_in[5];
    const float* w_col1 = (const float*)d_in[6];
    const float* w_col2 = (const float*)d_in[7];
    const float* w_vis0 = (const float*)d_in[8];
    const float* w_vis1 = (const float*)d_in[9];
    float* out = (float*)d_out;
    int N = in_sizes[0] / 32;

    cudaFuncSetAttribute(nerf_kernel, cudaFuncAttributeMaxDynamicSharedMemorySize,
                         SMEM_BYTES);

    prep_kernel<<<12, 256>>>(w_sig0, w_col0, w_vis0);

    int grid = (N + THREADS - 1) / THREADS;
    nerf_kernel<<<grid, THREADS, SMEM_BYTES>>>(x_feat, dv, lv, w_sig1, w_col1,
                                               w_col2, w_vis1, out, N);
}

// round 2
// speedup vs baseline: 1.0302x; 1.0302x over previous
#include <cuda_runtime.h>

typedef unsigned long long u64;

// ---------- packed f32x2 helpers (sm_103a) ----------
__device__ __forceinline__ u64 fma2(u64 a, u64 b, u64 c) {
    u64 d;
    asm("fma.rn.f32x2 %0, %1, %2, %3;" : "=l"(d) : "l"(a), "l"(b), "l"(c));
    return d;
}
__device__ __forceinline__ u64 pack2(float lo, float hi) {
    u64 d;
    asm("mov.b64 %0, {%1, %2};" : "=l"(d) : "f"(lo), "f"(hi));
    return d;
}
__device__ __forceinline__ float2 unpack2(u64 v) {
    float2 r;
    asm("mov.b64 {%0, %1}, %2;" : "=f"(r.x), "=f"(r.y) : "l"(v));
    return r;
}
__device__ __forceinline__ float red8(u64 a0, u64 a1, u64 a2, u64 a3) {
    float2 f0 = unpack2(a0), f1 = unpack2(a1), f2 = unpack2(a2), f3 = unpack2(a3);
    return ((f0.x + f0.y) + (f1.x + f1.y)) + ((f2.x + f2.y) + (f3.x + f3.y));
}

// ---------- transposed first-layer weights (scratch: __device__ globals) ----------
__device__ __align__(16) float g_sig0T[64 * 32];   // [out][in]
__device__ __align__(16) float g_col0T[64 * 64];
__device__ __align__(16) float g_vis0T[64 * 48];

__global__ void prep_kernel(const float* __restrict__ ws0,
                            const float* __restrict__ wc0,
                            const float* __restrict__ wv0) {
    int t = blockIdx.x * blockDim.x + threadIdx.x;
    int stride = gridDim.x * blockDim.x;
    for (int idx = t; idx < 64 * 32; idx += stride) {
        int j = idx >> 5, i = idx & 31;
        g_sig0T[idx] = ws0[i * 64 + j];
    }
    for (int idx = t; idx < 64 * 64; idx += stride) {
        int j = idx >> 6, i = idx & 63;
        g_col0T[idx] = wc0[i * 64 + j];
    }
    for (int idx = t; idx < 64 * 48; idx += stride) {
        int j = idx / 48, i = idx % 48;
        g_vis0T[idx] = wv0[i * 64 + j];
    }
}

// ---------- SH degree-4 (16 comps), matches reference ----------
__device__ __forceinline__ void sh16(float x, float y, float z, float* e) {
    float xx = x * x, yy = y * y, zz = z * z;
    float xy = x * y, yz = y * z, xz = x * z;
    e[0]  = 0.28209479177387814f;
    e[1]  = -0.48860251190291987f * y;
    e[2]  = 0.48860251190291987f * z;
    e[3]  = -0.48860251190291987f * x;
    e[4]  = 1.0925484305920792f * xy;
    e[5]  = -1.0925484305920792f * yz;
    e[6]  = 0.94617469575756f * zz - 0.31539156525252005f;
    e[7]  = -1.0925484305920792f * xz;
    e[8]  = 0.5462742152960396f * (xx - yy);
    e[9]  = 0.5900435899266435f * y * (3.0f * xx - yy);
    e[10] = 2.890611442640554f * xy * z;
    e[11] = 0.4570457994644657f * y * (4.0f * zz - xx - yy);
    e[12] = 0.3731763325901154f * z * (2.0f * zz - 3.0f * xx - 3.0f * yy);
    e[13] = 0.4570457994644657f * x * (4.0f * zz - xx - yy);
    e[14] = 1.445305721320277f * z * (xx - yy);
    e[15] = 0.5900435899266435f * x * (xx - 3.0f * yy);
}

#define THREADS 256
#define SMEM_FLOATS 15552   // 2048 + 1024 + 4096 + 5056 + 192 + 3072 + 64
#define SMEM_BYTES (SMEM_FLOATS * 4)

__global__ void __launch_bounds__(THREADS, 1)
nerf_kernel(const float* __restrict__ x_feat,
            const float* __restrict__ dvec,
            const float* __restrict__ lvec,
            const float* __restrict__ w_sig1,   // [64,16] row-major
            const float* __restrict__ w_col1,   // [79,64] row-major
            const float* __restrict__ w_col2,   // [64,3]  row-major
            const float* __restrict__ w_vis1,   // [64]
            float* __restrict__ out, int N) {
    extern __shared__ float sm[];
    float* s_sig0T = sm;            // 2048  [64][32]
    float* s_sig1  = sm + 2048;     // 1024  [64][16]
    float* s_col0T = sm + 3072;     // 4096  [64][64]
    float* s_col1  = sm + 7168;     // 5056  [79][64]
    float* s_col2  = sm + 12224;    // 192   [64][3]
    float* s_vis0T = sm + 12416;    // 3072  [64][48]
    float* s_vis1  = sm + 15488;    // 64

    // ---- cooperative weight staging (all float4, all sizes divisible by 4) ----
    {
        int t = threadIdx.x;
        const float4* s;
        s = (const float4*)g_sig0T;
        for (int i = t; i < 512; i += THREADS) ((float4*)s_sig0T)[i] = s[i];
        s = (const float4*)w_sig1;
        for (int i = t; i < 256; i += THREADS) ((float4*)s_sig1)[i] = s[i];
        s = (const float4*)g_col0T;
        for (int i = t; i < 1024; i += THREADS) ((float4*)s_col0T)[i] = s[i];
        s = (const float4*)w_col1;
        for (int i = t; i < 1264; i += THREADS) ((float4*)s_col1)[i] = s[i];
        s = (const float4*)w_col2;
        for (int i = t; i < 48; i += THREADS) ((float4*)s_col2)[i] = s[i];
        s = (const float4*)g_vis0T;
        for (int i = t; i < 768; i += THREADS) ((float4*)s_vis0T)[i] = s[i];
        s = (const float4*)w_vis1;
        if (t < 16) ((float4*)s_vis1)[t] = s[t];
    }
    __syncthreads();

    int n = blockIdx.x * THREADS + threadIdx.x;
    if (n >= N) return;

    // ---- per-point inputs ----
    float de[16], le[16];
    {
        const float* dp = dvec + 3 * (size_t)n;
        sh16(dp[0], dp[1], dp[2], de);
        const float* lp = lvec + 3 * (size_t)n;
        sh16(lp[0], lp[1], lp[2], le);
    }
    u64 pdv[8], plv[8], px[16];
#pragma unroll
    for (int i = 0; i < 8; i++) {
        pdv[i] = pack2(de[2 * i], de[2 * i + 1]);
        plv[i] = pack2(le[2 * i], le[2 * i + 1]);
    }
    {
        const ulonglong2* xp = (const ulonglong2*)(x_feat + 32 * (size_t)n);
#pragma unroll
        for (int i = 0; i < 8; i++) {
            ulonglong2 v = xp[i];
            px[2 * i] = v.x;
            px[2 * i + 1] = v.y;
        }
    }

    // ---- vis net: relu([x,l] @ w_vis0) @ w_vis1 -> sigmoid (fully fused) ----
    float visacc = 0.f;
#pragma unroll 4
    for (int j = 0; j < 64; j++) {
        const ulonglong2* w = (const ulonglong2*)(s_vis0T + j * 48);
        u64 a[4] = {0ull, 0ull, 0ull, 0ull};
#pragma unroll
        for (int ii = 0; ii < 8; ii++) {
            ulonglong2 wv = w[ii];
            a[(2 * ii) & 3]     = fma2(px[2 * ii],     wv.x, a[(2 * ii) & 3]);
            a[(2 * ii + 1) & 3] = fma2(px[2 * ii + 1], wv.y, a[(2 * ii + 1) & 3]);
        }
#pragma unroll
        for (int ii = 0; ii < 4; ii++) {
            ulonglong2 wv = w[8 + ii];
            a[(2 * ii) & 3]     = fma2(plv[2 * ii],     wv.x, a[(2 * ii) & 3]);
            a[(2 * ii + 1) & 3] = fma2(plv[2 * ii + 1], wv.y, a[(2 * ii + 1) & 3]);
        }
        float h = fmaxf(red8(a[0], a[1], a[2], a[3]), 0.f);
        visacc = fmaf(h, s_vis1[j], visacc);
    }
    float vis = __fdividef(1.f, 1.f + __expf(-visacc));

    // ---- sigma net: relu(x @ w_sig0) @ w_sig1; keep geo = out[1:16] ----
    u64 sa[8] = {0ull, 0ull, 0ull, 0ull, 0ull, 0ull, 0ull, 0ull};
#pragma unroll 4
    for (int j = 0; j < 64; j++) {
        const ulonglong2* w = (const ulonglong2*)(s_sig0T + j * 32);
        u64 a[4] = {0ull, 0ull, 0ull, 0ull};
#pragma unroll
        for (int ii = 0; ii < 8; ii++) {
            ulonglong2 wv = w[ii];
            a[(2 * ii) & 3]     = fma2(px[2 * ii],     wv.x, a[(2 * ii) & 3]);
            a[(2 * ii + 1) & 3] = fma2(px[2 * ii + 1], wv.y, a[(2 * ii + 1) & 3]);
        }
        float h = fmaxf(red8(a[0], a[1], a[2], a[3]), 0.f);
        u64 hh = pack2(h, h);
        const ulonglong2* w1 = (const ulonglong2*)(s_sig1 + j * 16);
#pragma unroll
        for (int ii = 0; ii < 4; ii++) {
            ulonglong2 wv = w1[ii];
            sa[2 * ii]     = fma2(hh, wv.x, sa[2 * ii]);
            sa[2 * ii + 1] = fma2(hh, wv.y, sa[2 * ii + 1]);
        }
    }
    float geo[15];
    {
        float2 p = unpack2(sa[0]);
        geo[0] = p.y;
#pragma unroll
        for (int k = 1; k < 8; k++) {
            p = unpack2(sa[k]);
            geo[2 * k - 1] = p.x;
            geo[2 * k] = p.y;
        }
    }

    // ---- color net: col0 fused into col1 accumulation ----
    u64 ca[32];
#pragma unroll
    for (int k = 0; k < 32; k++) ca[k] = 0ull;

#pragma unroll 2
    for (int j = 0; j < 64; j++) {
        const ulonglong2* w = (const ulonglong2*)(s_col0T + j * 64);
        u64 a[4] = {0ull, 0ull, 0ull, 0ull};
#pragma unroll
        for (int ii = 0; ii < 8; ii++) {   // x part (inputs 0..31)
            ulonglong2 wv = w[ii];
            a[(2 * ii) & 3]     = fma2(px[2 * ii],     wv.x, a[(2 * ii) & 3]);
            a[(2 * ii + 1) & 3] = fma2(px[2 * ii + 1], wv.y, a[(2 * ii + 1) & 3]);
        }
#pragma unroll
        for (int ii = 0; ii < 4; ii++) {   // l_enc part (32..47)
            ulonglong2 wv = w[8 + ii];
            a[(2 * ii) & 3]     = fma2(plv[2 * ii],     wv.x, a[(2 * ii) & 3]);
            a[(2 * ii + 1) & 3] = fma2(plv[2 * ii + 1], wv.y, a[(2 * ii + 1) & 3]);
        }
#pragma unroll
        for (int ii = 0; ii < 4; ii++) {   // d_enc part (48..63)
            ulonglong2 wv = w[12 + ii];
            a[(2 * ii) & 3]     = fma2(pdv[2 * ii],     wv.x, a[(2 * ii) & 3]);
            a[(2 * ii + 1) & 3] = fma2(pdv[2 * ii + 1], wv.y, a[(2 * ii + 1) & 3]);
        }
        float h = fmaxf(red8(a[0], a[1], a[2], a[3]), 0.f);
        u64 hh = pack2(h, h);
        const ulonglong2* w1 = (const ulonglong2*)(s_col1 + j * 64);
#pragma unroll
        for (int ii = 0; ii < 16; ii++) {
            ulonglong2 wv = w1[ii];
            ca[2 * ii]     = fma2(hh, wv.x, ca[2 * ii]);
            ca[2 * ii + 1] = fma2(hh, wv.y, ca[2 * ii + 1]);
        }
    }
    // geo tail of col1 input (rows 64..78)
#pragma unroll 3
    for (int g = 0; g < 15; g++) {
        u64 gg = pack2(geo[g], geo[g]);
        const ulonglong2* w1 = (const ulonglong2*)(s_col1 + (64 + g) * 64);
#pragma unroll
        for (int ii = 0; ii < 16; ii++) {
            ulonglong2 wv = w1[ii];
            ca[2 * ii]     = fma2(gg, wv.x, ca[2 * ii]);
            ca[2 * ii + 1] = fma2(gg, wv.y, ca[2 * ii + 1]);
        }
    }

    // ---- col2 + relu + vis scale ----
    float c0 = 0.f, c1 = 0.f, c2 = 0.f;
#pragma unroll
    for (int k2 = 0; k2 < 32; k2++) {
        float2 p = unpack2(ca[k2]);
        float v0 = fmaxf(p.x, 0.f), v1 = fmaxf(p.y, 0.f);
        const float* wr = s_col2 + 6 * k2;
        c0 = fmaf(v0, wr[0], c0);
        c1 = fmaf(v0, wr[1], c1);
        c2 = fmaf(v0, wr[2], c2);
        c0 = fmaf(v1, wr[3], c0);
        c1 = fmaf(v1, wr[4], c1);
        c2 = fmaf(v1, wr[5], c2);
    }
    float* o = out + 3 * (size_t)n;
    o[0] = fmaxf(c0, 0.f) * vis;
    o[1] = fmaxf(c1, 0.f) * vis;
    o[2] = fmaxf(c2, 0.f) * vis;
}

extern "C" void kernel_launch(void* const* d_in, const int* in_sizes, int n_in,
                              void* d_out, int out_size) {
    const float* x_feat = (const float*)d_in[0];
    const float* dv     = (const float*)d_in[1];
    const float* lv     = (const float*)d_in[2];
    const float* w_sig0 = (const float*)d_in[3];
    const float* w_sig1 = (const float*)d_in[4];
    const float* w_col0 = (const float*)d_in[5];
    const float* w_col1 = (const float*)d_in[6];
    const float* w_col2 = (const float*)d_in[7];
    const float* w_vis1 = (const float*)d_in[9];
    float* out = (float*)d_out;
    const float* w_vis0 = (const float*)d_in[8];
    int N = in_sizes[0] / 32;

    cudaFuncSetAttribute(nerf_kernel, cudaFuncAttributeMaxDynamicSharedMemorySize,
                         SMEM_BYTES);

    prep_kernel<<<12, 256>>>(w_sig0, w_col0, w_vis0);

    int grid = (N + THREADS - 1) / THREADS;
    nerf_kernel<<<grid, THREADS, SMEM_BYTES>>>(x_feat, dv, lv, w_sig1, w_col1,
                                               w_col2, w_vis1, out, N);
}